// round 1
// baseline (speedup 1.0000x reference)
#include <cuda_runtime.h>

#define NB 16
#define TT 1024
#define HH 1024
#define G3 3072
#define NCTA 128
#define NTHREADS 256
#define NTH_ELEMS (NB*TT*HH)

// scratch (static device allocations are the allowed scratch mechanism)
__device__ float    g_gx[(long long)NB*TT*G3];   // 192 MB: x @ w_i
__device__ float    g_rh[NB*HH];                 // r*h staging between phases
__device__ unsigned g_bar;                       // grid barrier counter

__global__ void reset_bar_kernel() {
    if (threadIdx.x == 0) g_bar = 0u;
}

// ---------------------------------------------------------------------------
// gx = x @ w_i   (M=16384, K=1024, N=3072) fp32 SGEMM, 128x128x8 tiles
// ---------------------------------------------------------------------------
__global__ void __launch_bounds__(256) gx_gemm_kernel(
        const float* __restrict__ A,   // x  [M][1024]
        const float* __restrict__ B) { // w_i[1024][3072]
    __shared__ float As[8][128];
    __shared__ float Bs[8][128];
    const int tid = threadIdx.x;
    const int bm = blockIdx.y * 128;
    const int bn = blockIdx.x * 128;
    const int tx = tid & 15;
    const int ty = tid >> 4;

    float acc[8][8];
#pragma unroll
    for (int i = 0; i < 8; i++)
#pragma unroll
        for (int j = 0; j < 8; j++) acc[i][j] = 0.f;

    const int arow = tid >> 1;
    const int acol = (tid & 1) * 4;
    const int brow = tid >> 5;
    const int bcol = (tid & 31) * 4;
    const float* Ap = A + (long long)(bm + arow) * HH + acol;
    const float* Bp = B + (long long)brow * G3 + bn + bcol;

    for (int k0 = 0; k0 < HH; k0 += 8) {
        float4 av = *(const float4*)Ap;
        float4 bv = *(const float4*)Bp;
        __syncthreads();  // protect smem from previous iteration's readers
        As[acol + 0][arow] = av.x;
        As[acol + 1][arow] = av.y;
        As[acol + 2][arow] = av.z;
        As[acol + 3][arow] = av.w;
        *(float4*)&Bs[brow][bcol] = bv;
        __syncthreads();
#pragma unroll
        for (int kk = 0; kk < 8; kk++) {
            float af[8], bf[8];
            *(float4*)&af[0] = *(const float4*)&As[kk][ty * 8];
            *(float4*)&af[4] = *(const float4*)&As[kk][ty * 8 + 4];
            *(float4*)&bf[0] = *(const float4*)&Bs[kk][tx * 8];
            *(float4*)&bf[4] = *(const float4*)&Bs[kk][tx * 8 + 4];
#pragma unroll
            for (int i = 0; i < 8; i++)
#pragma unroll
                for (int j = 0; j < 8; j++)
                    acc[i][j] = fmaf(af[i], bf[j], acc[i][j]);
        }
        Ap += 8;
        Bp += (long long)8 * G3;
    }
    float* Cp = g_gx + (long long)(bm + ty * 8) * G3 + bn + tx * 8;
#pragma unroll
    for (int i = 0; i < 8; i++) {
        *(float4*)(Cp + (long long)i * G3)     = *(float4*)&acc[i][0];
        *(float4*)(Cp + (long long)i * G3 + 4) = *(float4*)&acc[i][4];
    }
}

// ---------------------------------------------------------------------------
// persistent GRU scan: 128 CTAs, 8 hidden units each, grid barrier per phase
// ---------------------------------------------------------------------------
__device__ __forceinline__ void grid_barrier(unsigned target) {
    __syncthreads();
    if (threadIdx.x == 0) {
        __threadfence();
        atomicAdd(&g_bar, 1u);
        unsigned v;
        do { v = *((volatile unsigned*)&g_bar); } while (v < target);
        __threadfence();
    }
    __syncthreads();
}

__global__ void __launch_bounds__(256, 1) gru_scan_kernel(
        const void*  __restrict__ reset_raw,
        const float* __restrict__ carry,
        const float* __restrict__ initial_h,
        const float* __restrict__ w_h,
        const float* __restrict__ bias,
        float*       __restrict__ out) {
    extern __shared__ float smem[];
    float*  hs   = smem;             // 16 x 1024
    float*  rhs  = smem + NB * HH;   // 16 x 1024
    float4* hs4  = (float4*)hs;
    float4* rhs4 = (float4*)rhs;

    const int tid = threadIdx.x;
    const int jw  = tid >> 5;              // warp = hidden unit within CTA
    const int kc  = tid & 31;              // lane = K sub-chunk
    const int jg  = blockIdx.x * 8 + jw;   // global hidden index

    // ---- detect reset dtype: int32 / float32 / bool(byte) ----
    __shared__ int s_i32, s_f32;
    if (tid == 0) { s_i32 = 1; s_f32 = 1; }
    __syncthreads();
    {
        const unsigned* rw = (const unsigned*)reset_raw;
        int bad_i = 0, bad_f = 0;
        for (int q = tid; q < 4096; q += NTHREADS) {
            unsigned v = rw[q];
            if (v > 1u) bad_i = 1;
            if (v != 0u && v != 0x3F800000u) bad_f = 1;
        }
        if (bad_i) s_i32 = 0;
        if (bad_f) s_f32 = 0;
    }
    __syncthreads();
    const int rmode = s_i32 ? 0 : (s_f32 ? 1 : 2);
    const int*           r32 = (const int*)reset_raw;
    const float*         rf  = (const float*)reset_raw;
    const unsigned char* r8  = (const unsigned char*)reset_raw;

    // ---- third output: initial_h ----
    if (blockIdx.x == 0) {
        for (int q = tid; q < HH; q += NTHREADS)
            out[2 * (long long)NTH_ELEMS + q] = initial_h[q];
    }

    // ---- recurrent weights -> registers (persist across all 1024 steps) ----
    // thread covers k = 128*i + 4*kc + s,  i in [0,8), s in [0,4)
    float wz[32], wr[32], wa[32];
#pragma unroll
    for (int i = 0; i < 8; i++) {
#pragma unroll
        for (int s = 0; s < 4; s++) {
            int k = i * 128 + kc * 4 + s;
            const float* wrow = w_h + (long long)k * G3;
            wz[i * 4 + s] = wrow[jg];
            wr[i * 4 + s] = wrow[HH + jg];
            wa[i * 4 + s] = wrow[2 * HH + jg];
        }
    }
    const float bz = bias[jg], br = bias[HH + jg], ba = bias[2 * HH + jg];

    float z_keep = 0.f, h_keep = 0.f;

    for (int t = 0; t < TT; t++) {
        // ---- stage h_in (reset applied) into smem ----
#pragma unroll 4
        for (int p = 0; p < 16; p++) {
            int q  = tid + NTHREADS * p;   // float4 index, 0..4095
            int n  = q >> 8;
            int kf = q & 255;
            bool rst = (rmode == 0) ? (r32[n * TT + t] != 0)
                     : (rmode == 1) ? (rf[n * TT + t] != 0.f)
                                    : (r8[n * TT + t] != 0);
            float4 v;
            if (rst)
                v = *(const float4*)(initial_h + kf * 4);
            else if (t == 0)
                v = *(const float4*)(carry + (long long)n * TT * HH + kf * 4);
            else
                v = *(const float4*)(out + (long long)(n * TT + (t - 1)) * HH + kf * 4);
            hs4[q] = v;
        }
        __syncthreads();

        // ---- phase A: z & r partial sums over this lane's 32 k's ----
        float accz[16], accr[16];
#pragma unroll
        for (int n = 0; n < 16; n++) { accz[n] = 0.f; accr[n] = 0.f; }
#pragma unroll
        for (int n = 0; n < 16; n += 2) {
#pragma unroll
            for (int i = 0; i < 8; i++) {
                float4 h0 = hs4[(n << 8) + (i << 5) + kc];
                float4 h1 = hs4[((n + 1) << 8) + (i << 5) + kc];
                const float* p0 = (const float*)&h0;
                const float* p1 = (const float*)&h1;
#pragma unroll
                for (int s = 0; s < 4; s++) {
                    accz[n]     = fmaf(p0[s], wz[i * 4 + s], accz[n]);
                    accr[n]     = fmaf(p0[s], wr[i * 4 + s], accr[n]);
                    accz[n + 1] = fmaf(p1[s], wz[i * 4 + s], accz[n + 1]);
                    accr[n + 1] = fmaf(p1[s], wr[i * 4 + s], accr[n + 1]);
                }
            }
        }
#pragma unroll
        for (int n = 0; n < 16; n++) {
#pragma unroll
            for (int off = 16; off > 0; off >>= 1) {
                accz[n] += __shfl_xor_sync(0xffffffffu, accz[n], off);
                accr[n] += __shfl_xor_sync(0xffffffffu, accr[n], off);
            }
        }
        if (kc < 16) {
            float zs = 0.f, rs = 0.f;
#pragma unroll
            for (int n = 0; n < 16; n++)
                if (kc == n) { zs = accz[n]; rs = accr[n]; }
            int n = kc;
            float hold = hs[(n << 10) + jg];
            long long gbase = ((long long)(n * TT + t)) * G3;
            float gz = g_gx[gbase + jg];
            float gr = g_gx[gbase + HH + jg];
            float z = 1.f / (1.f + __expf(-(gz + zs + bz)));
            float r = 1.f / (1.f + __expf(-(gr + rs + br)));
            g_rh[(n << 10) + jg] = r * hold;
            z_keep = z;
            h_keep = hold;
        }

        grid_barrier((unsigned)(2 * t + 1) * NCTA);

        // ---- stage r*h (L2-only loads: addresses are reused every step) ----
#pragma unroll 4
        for (int p = 0; p < 16; p++) {
            int q = tid + NTHREADS * p;
            rhs4[q] = __ldcg(((const float4*)g_rh) + q);
        }
        __syncthreads();

        // ---- phase B: a-gate ----
        float acca[16];
#pragma unroll
        for (int n = 0; n < 16; n++) acca[n] = 0.f;
#pragma unroll
        for (int n = 0; n < 16; n += 2) {
#pragma unroll
            for (int i = 0; i < 8; i++) {
                float4 h0 = rhs4[(n << 8) + (i << 5) + kc];
                float4 h1 = rhs4[((n + 1) << 8) + (i << 5) + kc];
                const float* p0 = (const float*)&h0;
                const float* p1 = (const float*)&h1;
#pragma unroll
                for (int s = 0; s < 4; s++) {
                    acca[n]     = fmaf(p0[s], wa[i * 4 + s], acca[n]);
                    acca[n + 1] = fmaf(p1[s], wa[i * 4 + s], acca[n + 1]);
                }
            }
        }
#pragma unroll
        for (int n = 0; n < 16; n++) {
#pragma unroll
            for (int off = 16; off > 0; off >>= 1)
                acca[n] += __shfl_xor_sync(0xffffffffu, acca[n], off);
        }
        if (kc < 16) {
            float as = 0.f;
#pragma unroll
            for (int n = 0; n < 16; n++)
                if (kc == n) as = acca[n];
            int n = kc;
            long long gbase = ((long long)(n * TT + t)) * G3;
            float ga = g_gx[gbase + 2 * HH + jg];
            float a  = tanhf(ga + as + ba);
            float hn = (1.f - z_keep) * h_keep + z_keep * a;
            long long oidx = ((long long)(n * TT + t)) * HH + jg;
            out[oidx]             = hn;
            out[NTH_ELEMS + oidx] = hn;
        }

        grid_barrier((unsigned)(2 * t + 2) * NCTA);
    }
}

// ---------------------------------------------------------------------------
extern "C" void kernel_launch(void* const* d_in, const int* in_sizes, int n_in,
                              void* d_out, int out_size) {
    const float* x         = (const float*)d_in[0];
    const void*  reset     = d_in[1];
    const float* carry     = (const float*)d_in[2];
    const float* initial_h = (const float*)d_in[3];
    const float* w_i       = (const float*)d_in[4];
    const float* w_h       = (const float*)d_in[5];
    const float* b         = (const float*)d_in[6];
    float*       out       = (float*)d_out;
    (void)in_sizes; (void)n_in; (void)out_size;

    reset_bar_kernel<<<1, 32>>>();

    dim3 ggrid(G3 / 128, (NB * TT) / 128);
    gx_gemm_kernel<<<ggrid, 256>>>(x, w_i);

    size_t smem = (size_t)2 * NB * HH * sizeof(float);  // 128 KB
    cudaFuncSetAttribute((const void*)gru_scan_kernel,
                         cudaFuncAttributeMaxDynamicSharedMemorySize, (int)smem);
    gru_scan_kernel<<<NCTA, NTHREADS, smem>>>(reset, carry, initial_h, w_h, b, out);
}

// round 2
// speedup vs baseline: 1.5077x; 1.5077x over previous
#include <cuda_runtime.h>

#define NB 16
#define TT 1024
#define HH 1024
#define G3 3072
#define NCTA 128
#define STHR 512
#define NTH_ELEMS (NB*TT*HH)

typedef unsigned long long u64;

// scratch
__device__ float    g_gx[(long long)NB*TT*G3];   // 192 MB: x @ w_i
__device__ float    g_rh[NB*HH];                 // r*h staging between phases
__device__ unsigned g_bar;                       // grid barrier counter

// ---- packed fp32x2 helpers (Blackwell dual-issue FP32 path) ----
__device__ __forceinline__ void fma2(u64& d, u64 a, u64 b) {
    asm("fma.rn.f32x2 %0, %1, %2, %0;" : "+l"(d) : "l"(a), "l"(b));
}
__device__ __forceinline__ u64 dup2(float x) {
    u64 r; asm("mov.b64 %0, {%1, %1};" : "=l"(r) : "f"(x)); return r;
}
__device__ __forceinline__ float2 unpk(u64 v) {
    float2 r; asm("mov.b64 {%0, %1}, %2;" : "=f"(r.x), "=f"(r.y) : "l"(v)); return r;
}

// ---------------------------------------------------------------------------
// gx = x @ w_i  (M=16384, K=1024, N=3072) fp32 via packed FFMA2, 128x128x8
// ---------------------------------------------------------------------------
__global__ void __launch_bounds__(256, 2) gx_gemm_kernel(
        const float* __restrict__ A,   // x  [M][1024]
        const float* __restrict__ B) { // w_i[1024][3072]
    __shared__ float As[2][8][128];
    __shared__ float Bs[2][8][128];

    if (blockIdx.x == 0 && blockIdx.y == 0 && threadIdx.x == 0)
        g_bar = 0u;   // fold barrier reset here (runs before scan on stream)

    const int tid = threadIdx.x;
    const int bm = blockIdx.y * 128;
    const int bn = blockIdx.x * 128;
    const int tx = tid & 15;
    const int ty = tid >> 4;

    u64 acc2[8][4];
#pragma unroll
    for (int i = 0; i < 8; i++)
#pragma unroll
        for (int j = 0; j < 4; j++) acc2[i][j] = 0ull;

    const int arow = tid >> 1;
    const int acol = (tid & 1) * 4;
    const int brow = tid >> 5;
    const int bcol = (tid & 31) * 4;
    const float* Ap = A + (size_t)(bm + arow) * HH + acol;
    const float* Bp = B + (size_t)brow * G3 + bn + bcol;

    // preload + store tile 0
    float4 av = *(const float4*)Ap;
    float4 bv = *(const float4*)Bp;
    As[0][acol + 0][arow] = av.x;
    As[0][acol + 1][arow] = av.y;
    As[0][acol + 2][arow] = av.z;
    As[0][acol + 3][arow] = av.w;
    *(float4*)&Bs[0][brow][bcol] = bv;

    for (int it = 0; it < 128; it++) {
        __syncthreads();   // buffer (it&1) fully stored
        const int db = it & 1;
        if (it < 127) {    // prefetch next tile from global
            Ap += 8;
            Bp += (size_t)8 * G3;
            av = *(const float4*)Ap;
            bv = *(const float4*)Bp;
        }
#pragma unroll
        for (int kk = 0; kk < 8; kk++) {
            float4 a0 = *(const float4*)&As[db][kk][ty * 8];
            float4 a1 = *(const float4*)&As[db][kk][ty * 8 + 4];
            ulonglong2 b01 = *(const ulonglong2*)&Bs[db][kk][tx * 8];
            ulonglong2 b23 = *(const ulonglong2*)&Bs[db][kk][tx * 8 + 4];
            u64 ad[8];
            ad[0] = dup2(a0.x); ad[1] = dup2(a0.y);
            ad[2] = dup2(a0.z); ad[3] = dup2(a0.w);
            ad[4] = dup2(a1.x); ad[5] = dup2(a1.y);
            ad[6] = dup2(a1.z); ad[7] = dup2(a1.w);
#pragma unroll
            for (int i = 0; i < 8; i++) {
                fma2(acc2[i][0], ad[i], b01.x);
                fma2(acc2[i][1], ad[i], b01.y);
                fma2(acc2[i][2], ad[i], b23.x);
                fma2(acc2[i][3], ad[i], b23.y);
            }
        }
        if (it < 127) {    // store next tile into other buffer
            const int nb = db ^ 1;
            As[nb][acol + 0][arow] = av.x;
            As[nb][acol + 1][arow] = av.y;
            As[nb][acol + 2][arow] = av.z;
            As[nb][acol + 3][arow] = av.w;
            *(float4*)&Bs[nb][brow][bcol] = bv;
        }
    }

    float* Cp = g_gx + (size_t)(bm + ty * 8) * G3 + bn + tx * 8;
#pragma unroll
    for (int i = 0; i < 8; i++) {
        float2 c0 = unpk(acc2[i][0]);
        float2 c1 = unpk(acc2[i][1]);
        float2 c2 = unpk(acc2[i][2]);
        float2 c3 = unpk(acc2[i][3]);
        float4 lo = make_float4(c0.x, c0.y, c1.x, c1.y);
        float4 hi = make_float4(c2.x, c2.y, c3.x, c3.y);
        *(float4*)(Cp + (size_t)i * G3)     = lo;
        *(float4*)(Cp + (size_t)i * G3 + 4) = hi;
    }
}

// ---------------------------------------------------------------------------
// grid barrier: release-add arrive, acquire-load spin (thread 0 only)
// ---------------------------------------------------------------------------
__device__ __forceinline__ void grid_barrier(unsigned target) {
    __syncthreads();
    if (threadIdx.x == 0) {
        asm volatile("red.release.gpu.global.add.u32 [%0], 1;"
                     :: "l"(&g_bar) : "memory");
        unsigned v;
        do {
            asm volatile("ld.acquire.gpu.global.u32 %0, [%1];"
                         : "=r"(v) : "l"(&g_bar) : "memory");
        } while (v < target);
    }
    __syncthreads();
}

// ---------------------------------------------------------------------------
// persistent GRU scan: 128 CTAs x 512 threads; 8 hidden units per CTA,
// 2 warps per hidden unit (k split in halves of 512)
// ---------------------------------------------------------------------------
__global__ void __launch_bounds__(STHR, 1) gru_scan_kernel(
        const void*  __restrict__ reset_raw,
        const float* __restrict__ carry,
        const float* __restrict__ initial_h,
        const float* __restrict__ w_h,
        const float* __restrict__ bias,
        float*       __restrict__ out) {
    extern __shared__ char smc[];
    float*    hs    = (float*)smc;                 // 64 KB: h staged
    float*    rhs   = (float*)(smc + 65536);       // 64 KB: r*h staged
    unsigned* rbits = (unsigned*)(smc + 131072);   //  4 KB: reset masks
    float2*   pzr   = (float2*)(smc + 135168);     //  2 KB: [khalf][j][n]
    float*    pa    = (float*)(smc + 137216);      //  1 KB
    float*    z_s   = (float*)(smc + 138240);      // 512 B: z per (n,j)
    float*    rh_s  = (float*)(smc + 138752);      // 512 B
    float*    ho_s  = (float*)(smc + 139264);      // 512 B
    float4*   hs4   = (float4*)hs;
    float4*   rhs4  = (float4*)rhs;

    const int tid   = threadIdx.x;
    const int w     = tid >> 5;
    const int jw    = w >> 1;          // hidden unit within CTA (0..7)
    const int khalf = w & 1;           // k half (0..1)
    const int kc    = tid & 31;
    const int jbase = blockIdx.x * 8;
    const int jg    = jbase + jw;

    // ---- detect reset dtype ----
    __shared__ int s_i32, s_f32;
    if (tid == 0) { s_i32 = 1; s_f32 = 1; }
    __syncthreads();
    {
        const unsigned* rw = (const unsigned*)reset_raw;
        int bad_i = 0, bad_f = 0;
        for (int q = tid; q < 4096; q += STHR) {
            unsigned v = rw[q];
            if (v > 1u) bad_i = 1;
            if (v != 0u && v != 0x3F800000u) bad_f = 1;
        }
        if (bad_i) s_i32 = 0;
        if (bad_f) s_f32 = 0;
    }
    __syncthreads();
    const int rmode = s_i32 ? 0 : (s_f32 ? 1 : 2);
    const int*           r32 = (const int*)reset_raw;
    const float*         rf  = (const float*)reset_raw;
    const unsigned char* r8  = (const unsigned char*)reset_raw;

    // ---- precompute reset bitmasks per timestep ----
    for (int t0 = tid; t0 < TT; t0 += STHR) {
        unsigned m = 0;
#pragma unroll
        for (int n = 0; n < NB; n++) {
            bool rv = (rmode == 0) ? (r32[n * TT + t0] != 0)
                    : (rmode == 1) ? (rf[n * TT + t0] != 0.f)
                                   : (r8[n * TT + t0] != 0);
            m |= (unsigned)rv << n;
        }
        rbits[t0] = m;
    }

    // ---- third output: initial_h ----
    if (blockIdx.x == 0)
        for (int q = tid; q < HH; q += STHR)
            out[2 * (size_t)NTH_ELEMS + q] = initial_h[q];

    // ---- recurrent weights -> registers: 16 k values per thread ----
    float wz[16], wr[16], wa[16];
#pragma unroll
    for (int i = 0; i < 4; i++) {
#pragma unroll
        for (int s = 0; s < 4; s++) {
            int k = (khalf << 9) + (i << 7) + (kc << 2) + s;
            const float* wrow = w_h + (size_t)k * G3;
            wz[i * 4 + s] = wrow[jg];
            wr[i * 4 + s] = wrow[HH + jg];
            wa[i * 4 + s] = wrow[2 * HH + jg];
        }
    }

    // combine-thread private state (tid < 128: j = tid>>4, n = tid&15)
    const int j_c = tid >> 4;
    const int n_c = tid & 15;
    float bz = 0.f, br = 0.f, ba = 0.f;
    if (tid < 128) {
        bz = bias[jbase + j_c];
        br = bias[HH + jbase + j_c];
        ba = bias[2 * HH + jbase + j_c];
    }

    const float4* ih4    = (const float4*)initial_h;
    const float4* g_rh4c = (const float4*)g_rh;

    __syncthreads();   // rbits ready

    for (int t = 0; t < TT; t++) {
        const unsigned mask = rbits[t];
        const float4* base4 = (t == 0) ? (const float4*)carry : (const float4*)out;
        const int     off4  = (t == 0) ? 0 : (t - 1) * (HH / 4);

        // gx prefetch for combine threads (in flight behind staging)
        float gxz = 0.f, gxr = 0.f, gxa = 0.f;
        if (tid < 128) {
            size_t gb = ((size_t)(n_c * TT + t)) * G3 + jbase + j_c;
            gxz = g_gx[gb];
            gxr = g_gx[gb + HH];
            gxa = g_gx[gb + 2 * HH];
        }

        // ---- stage h_in (reset applied), MLP-4 rounds ----
#pragma unroll
        for (int r0 = 0; r0 < 8; r0 += 4) {
            float4 v[4];
#pragma unroll
            for (int p = 0; p < 4; p++) {
                int q  = tid + ((r0 + p) << 9);
                int n  = q >> 8;
                int kf = q & 255;
                const float4* src = ((mask >> n) & 1u)
                        ? (ih4 + kf)
                        : (base4 + (size_t)n * (TT * HH / 4) + off4 + kf);
                v[p] = *src;
            }
#pragma unroll
            for (int p = 0; p < 4; p++)
                hs4[tid + ((r0 + p) << 9)] = v[p];
        }
        __syncthreads();

        // ---- phase A: z,r partial dots (2 passes of 8 batches) ----
#pragma unroll
        for (int pass = 0; pass < 2; pass++) {
            float accz[8], accr[8];
#pragma unroll
            for (int m = 0; m < 8; m++) { accz[m] = 0.f; accr[m] = 0.f; }
#pragma unroll
            for (int m = 0; m < 8; m++) {
                const int n = pass * 8 + m;
#pragma unroll
                for (int i = 0; i < 4; i++) {
                    float4 h = hs4[(n << 8) + (khalf << 7) + (i << 5) + kc];
                    accz[m] = fmaf(h.x, wz[i * 4 + 0], accz[m]);
                    accr[m] = fmaf(h.x, wr[i * 4 + 0], accr[m]);
                    accz[m] = fmaf(h.y, wz[i * 4 + 1], accz[m]);
                    accr[m] = fmaf(h.y, wr[i * 4 + 1], accr[m]);
                    accz[m] = fmaf(h.z, wz[i * 4 + 2], accz[m]);
                    accr[m] = fmaf(h.z, wr[i * 4 + 2], accr[m]);
                    accz[m] = fmaf(h.w, wz[i * 4 + 3], accz[m]);
                    accr[m] = fmaf(h.w, wr[i * 4 + 3], accr[m]);
                }
            }
#pragma unroll
            for (int m = 0; m < 8; m++) {
#pragma unroll
                for (int off = 16; off > 0; off >>= 1) {
                    accz[m] += __shfl_xor_sync(0xffffffffu, accz[m], off);
                    accr[m] += __shfl_xor_sync(0xffffffffu, accr[m], off);
                }
            }
            if (kc < 8) {
                float az = 0.f, ar = 0.f;
#pragma unroll
                for (int m = 0; m < 8; m++)
                    if (kc == m) { az = accz[m]; ar = accr[m]; }
                pzr[((khalf << 3) + jw) * 16 + pass * 8 + kc] = make_float2(az, ar);
            }
        }
        __syncthreads();

        // ---- combine A: gates, r*h ----
        if (tid < 128) {
            float2 q0 = pzr[(0 + j_c) * 16 + n_c];
            float2 q1 = pzr[(8 + j_c) * 16 + n_c];
            float hold = hs[(n_c << 10) + jbase + j_c];
            float z = 1.f / (1.f + __expf(-(gxz + q0.x + q1.x + bz)));
            float r = 1.f / (1.f + __expf(-(gxr + q0.y + q1.y + br)));
            z_s[n_c * 8 + j_c]  = z;
            rh_s[n_c * 8 + j_c] = r * hold;
        }
        __syncthreads();
        if (tid < 32) {
            int n = tid >> 1, h2 = tid & 1;
            *(float4*)&g_rh[(n << 10) + jbase + h2 * 4] =
                *(float4*)&rh_s[n * 8 + h2 * 4];
        }

        grid_barrier((unsigned)(2 * t + 1) * NCTA);

        // ---- stage r*h (L2-only: addresses reused every step) ----
#pragma unroll
        for (int r0 = 0; r0 < 8; r0 += 4) {
            float4 v[4];
#pragma unroll
            for (int p = 0; p < 4; p++)
                v[p] = __ldcg(g_rh4c + tid + ((r0 + p) << 9));
#pragma unroll
            for (int p = 0; p < 4; p++)
                rhs4[tid + ((r0 + p) << 9)] = v[p];
        }
        __syncthreads();

        // ---- phase B: a-gate partial dots ----
#pragma unroll
        for (int pass = 0; pass < 2; pass++) {
            float acca[8];
#pragma unroll
            for (int m = 0; m < 8; m++) acca[m] = 0.f;
#pragma unroll
            for (int m = 0; m < 8; m++) {
                const int n = pass * 8 + m;
#pragma unroll
                for (int i = 0; i < 4; i++) {
                    float4 h = rhs4[(n << 8) + (khalf << 7) + (i << 5) + kc];
                    acca[m] = fmaf(h.x, wa[i * 4 + 0], acca[m]);
                    acca[m] = fmaf(h.y, wa[i * 4 + 1], acca[m]);
                    acca[m] = fmaf(h.z, wa[i * 4 + 2], acca[m]);
                    acca[m] = fmaf(h.w, wa[i * 4 + 3], acca[m]);
                }
            }
#pragma unroll
            for (int m = 0; m < 8; m++) {
#pragma unroll
                for (int off = 16; off > 0; off >>= 1)
                    acca[m] += __shfl_xor_sync(0xffffffffu, acca[m], off);
            }
            if (kc < 8) {
                float aa = 0.f;
#pragma unroll
                for (int m = 0; m < 8; m++)
                    if (kc == m) aa = acca[m];
                pa[((khalf << 3) + jw) * 16 + pass * 8 + kc] = aa;
            }
        }
        __syncthreads();

        // ---- combine B: h_next ----
        if (tid < 128) {
            float s0 = pa[(0 + j_c) * 16 + n_c];
            float s1 = pa[(8 + j_c) * 16 + n_c];
            float a  = tanhf(gxa + s0 + s1 + ba);
            float z  = z_s[n_c * 8 + j_c];
            float hold = hs[(n_c << 10) + jbase + j_c];
            ho_s[n_c * 8 + j_c] = (1.f - z) * hold + z * a;
        }
        __syncthreads();
        if (tid < 64) {
            int idx = tid & 31, cp = tid >> 5;
            int n = idx >> 1, h2 = idx & 1;
            float4 v = *(float4*)&ho_s[n * 8 + h2 * 4];
            *(float4*)(out + (size_t)cp * NTH_ELEMS +
                       ((size_t)(n * TT + t)) * HH + jbase + h2 * 4) = v;
        }

        grid_barrier((unsigned)(2 * t + 2) * NCTA);
    }
}

// ---------------------------------------------------------------------------
extern "C" void kernel_launch(void* const* d_in, const int* in_sizes, int n_in,
                              void* d_out, int out_size) {
    const float* x         = (const float*)d_in[0];
    const void*  reset     = d_in[1];
    const float* carry     = (const float*)d_in[2];
    const float* initial_h = (const float*)d_in[3];
    const float* w_i       = (const float*)d_in[4];
    const float* w_h       = (const float*)d_in[5];
    const float* b         = (const float*)d_in[6];
    float*       out       = (float*)d_out;
    (void)in_sizes; (void)n_in; (void)out_size;

    dim3 ggrid(G3 / 128, (NB * TT) / 128);
    gx_gemm_kernel<<<ggrid, 256>>>(x, w_i);

    size_t smem = 139776;
    cudaFuncSetAttribute((const void*)gru_scan_kernel,
                         cudaFuncAttributeMaxDynamicSharedMemorySize, (int)smem);
    gru_scan_kernel<<<NCTA, STHR, smem>>>(reset, carry, initial_h, w_h, b, out);
}

// round 3
// speedup vs baseline: 1.5995x; 1.0609x over previous
#include <cuda_runtime.h>

#define NB 16
#define TT 1024
#define HH 1024
#define G3 3072
#define NCTA 128
#define STHR 512
#define NTH_ELEMS (NB*TT*HH)

typedef unsigned long long u64;

// scratch
__device__ float    g_gx[(long long)NB*TT*G3];   // 192 MB: x @ w_i
__device__ float    g_rh[NB*HH];                 // r*h staging between phases
__device__ unsigned g_bar;                       // grid barrier counter

// ---- packed fp32x2 helpers ----
__device__ __forceinline__ void fma2(u64& d, u64 a, u64 b) {
    asm("fma.rn.f32x2 %0, %1, %2, %0;" : "+l"(d) : "l"(a), "l"(b));
}
__device__ __forceinline__ u64 dup2(float x) {
    u64 r; asm("mov.b64 %0, {%1, %1};" : "=l"(r) : "f"(x)); return r;
}
__device__ __forceinline__ u64 pk2(float lo, float hi) {
    u64 r; asm("mov.b64 %0, {%1, %2};" : "=l"(r) : "f"(lo), "f"(hi)); return r;
}
__device__ __forceinline__ float2 unpk(u64 v) {
    float2 r; asm("mov.b64 {%0, %1}, %2;" : "=f"(r.x), "=f"(r.y) : "l"(v)); return r;
}

// ---------------------------------------------------------------------------
// gx = x @ w_i  (M=16384, K=1024, N=3072) fp32 via packed FFMA2, 128x128x8
// ---------------------------------------------------------------------------
__global__ void __launch_bounds__(256, 2) gx_gemm_kernel(
        const float* __restrict__ A,
        const float* __restrict__ B) {
    __shared__ float As[2][8][128];
    __shared__ float Bs[2][8][128];

    if (blockIdx.x == 0 && blockIdx.y == 0 && threadIdx.x == 0)
        g_bar = 0u;   // barrier reset for the scan (same stream, runs first)

    const int tid = threadIdx.x;
    const int bm = blockIdx.y * 128;
    const int bn = blockIdx.x * 128;
    const int tx = tid & 15;
    const int ty = tid >> 4;

    u64 acc2[8][4];
#pragma unroll
    for (int i = 0; i < 8; i++)
#pragma unroll
        for (int j = 0; j < 4; j++) acc2[i][j] = 0ull;

    const int arow = tid >> 1;
    const int acol = (tid & 1) * 4;
    const int brow = tid >> 5;
    const int bcol = (tid & 31) * 4;
    const float* Ap = A + (size_t)(bm + arow) * HH + acol;
    const float* Bp = B + (size_t)brow * G3 + bn + bcol;

    float4 av = *(const float4*)Ap;
    float4 bv = *(const float4*)Bp;
    As[0][acol + 0][arow] = av.x;
    As[0][acol + 1][arow] = av.y;
    As[0][acol + 2][arow] = av.z;
    As[0][acol + 3][arow] = av.w;
    *(float4*)&Bs[0][brow][bcol] = bv;

    for (int it = 0; it < 128; it++) {
        __syncthreads();
        const int db = it & 1;
        if (it < 127) {
            Ap += 8;
            Bp += (size_t)8 * G3;
            av = *(const float4*)Ap;
            bv = *(const float4*)Bp;
        }
#pragma unroll
        for (int kk = 0; kk < 8; kk++) {
            float4 a0 = *(const float4*)&As[db][kk][ty * 8];
            float4 a1 = *(const float4*)&As[db][kk][ty * 8 + 4];
            ulonglong2 b01 = *(const ulonglong2*)&Bs[db][kk][tx * 8];
            ulonglong2 b23 = *(const ulonglong2*)&Bs[db][kk][tx * 8 + 4];
            u64 ad[8];
            ad[0] = dup2(a0.x); ad[1] = dup2(a0.y);
            ad[2] = dup2(a0.z); ad[3] = dup2(a0.w);
            ad[4] = dup2(a1.x); ad[5] = dup2(a1.y);
            ad[6] = dup2(a1.z); ad[7] = dup2(a1.w);
#pragma unroll
            for (int i = 0; i < 8; i++) {
                fma2(acc2[i][0], ad[i], b01.x);
                fma2(acc2[i][1], ad[i], b01.y);
                fma2(acc2[i][2], ad[i], b23.x);
                fma2(acc2[i][3], ad[i], b23.y);
            }
        }
        if (it < 127) {
            const int nb = db ^ 1;
            As[nb][acol + 0][arow] = av.x;
            As[nb][acol + 1][arow] = av.y;
            As[nb][acol + 2][arow] = av.z;
            As[nb][acol + 3][arow] = av.w;
            *(float4*)&Bs[nb][brow][bcol] = bv;
        }
    }

    float* Cp = g_gx + (size_t)(bm + ty * 8) * G3 + bn + tx * 8;
#pragma unroll
    for (int i = 0; i < 8; i++) {
        float2 c0 = unpk(acc2[i][0]);
        float2 c1 = unpk(acc2[i][1]);
        float2 c2 = unpk(acc2[i][2]);
        float2 c3 = unpk(acc2[i][3]);
        *(float4*)(Cp + (size_t)i * G3)     = make_float4(c0.x, c0.y, c1.x, c1.y);
        *(float4*)(Cp + (size_t)i * G3 + 4) = make_float4(c2.x, c2.y, c3.x, c3.y);
    }
}

// ---------------------------------------------------------------------------
__device__ __forceinline__ void grid_barrier(unsigned target) {
    __syncthreads();
    if (threadIdx.x == 0) {
        asm volatile("red.release.gpu.global.add.u32 [%0], 1;"
                     :: "l"(&g_bar) : "memory");
        unsigned v;
        do {
            asm volatile("ld.acquire.gpu.global.u32 %0, [%1];"
                         : "=r"(v) : "l"(&g_bar) : "memory");
        } while (v < target);
    }
    __syncthreads();
}

// ---------------------------------------------------------------------------
// persistent GRU scan: 128 CTAs x 512 threads; 8 hidden units per CTA,
// 2 warps per hidden unit (k split in halves); packed FFMA2; 3-level trees
// ---------------------------------------------------------------------------
__global__ void __launch_bounds__(STHR, 1) gru_scan_kernel(
        const void*  __restrict__ reset_raw,
        const float* __restrict__ carry,
        const float* __restrict__ initial_h,
        const float* __restrict__ w_h,
        const float* __restrict__ bias,
        float*       __restrict__ out) {
    extern __shared__ char smc[];
    float*    hs    = (float*)smc;                 // 64 KB
    float*    rhs   = (float*)(smc + 65536);       // 64 KB
    unsigned* rbits = (unsigned*)(smc + 131072);   //  4 KB
    float2*   pzr   = (float2*)(smc + 135168);     //  8 KB: [khalf8+j][n][slot]
    float*    pa    = (float*)(smc + 143360);      //  4 KB
    float4*   hs4   = (float4*)hs;
    float4*   rhs4  = (float4*)rhs;

    const int tid   = threadIdx.x;
    const int w     = tid >> 5;
    const int jw    = w >> 1;
    const int khalf = w & 1;
    const int kc    = tid & 31;
    const int jbase = blockIdx.x * 8;
    const int jg    = jbase + jw;

    // ---- detect reset dtype ----
    __shared__ int s_i32, s_f32;
    if (tid == 0) { s_i32 = 1; s_f32 = 1; }
    __syncthreads();
    {
        const unsigned* rw = (const unsigned*)reset_raw;
        int bad_i = 0, bad_f = 0;
        for (int q = tid; q < 4096; q += STHR) {
            unsigned v = rw[q];
            if (v > 1u) bad_i = 1;
            if (v != 0u && v != 0x3F800000u) bad_f = 1;
        }
        if (bad_i) s_i32 = 0;
        if (bad_f) s_f32 = 0;
    }
    __syncthreads();
    const int rmode = s_i32 ? 0 : (s_f32 ? 1 : 2);
    const int*           r32 = (const int*)reset_raw;
    const float*         rf  = (const float*)reset_raw;
    const unsigned char* r8  = (const unsigned char*)reset_raw;

    for (int t0 = tid; t0 < TT; t0 += STHR) {
        unsigned m = 0;
#pragma unroll
        for (int n = 0; n < NB; n++) {
            bool rv = (rmode == 0) ? (r32[n * TT + t0] != 0)
                    : (rmode == 1) ? (rf[n * TT + t0] != 0.f)
                                   : (r8[n * TT + t0] != 0);
            m |= (unsigned)rv << n;
        }
        rbits[t0] = m;
    }

    if (blockIdx.x == 0)
        for (int q = tid; q < HH; q += STHR)
            out[2 * (size_t)NTH_ELEMS + q] = initial_h[q];

    // ---- packed recurrent weights: 8 u64 per gate per thread ----
    u64 wz2[8], wr2[8], wa2[8];
#pragma unroll
    for (int i = 0; i < 4; i++) {
#pragma unroll
        for (int p = 0; p < 2; p++) {
            int k0 = (khalf << 9) + (i << 7) + (kc << 2) + p * 2;
            const float* w0 = w_h + (size_t)k0 * G3;
            const float* w1 = w_h + (size_t)(k0 + 1) * G3;
            wz2[i * 2 + p] = pk2(w0[jg],          w1[jg]);
            wr2[i * 2 + p] = pk2(w0[HH + jg],     w1[HH + jg]);
            wa2[i * 2 + p] = pk2(w0[2 * HH + jg], w1[2 * HH + jg]);
        }
    }

    // combine-thread (tid<128) state
    const int j_c = tid >> 4;
    const int n_c = tid & 15;
    float bz = 0.f, br = 0.f, ba = 0.f;
    if (tid < 128) {
        bz = bias[jbase + j_c];
        br = bias[HH + jbase + j_c];
        ba = bias[2 * HH + jbase + j_c];
    }
    float z_keep = 0.f, h_keep = 0.f;

    const float4* ih4    = (const float4*)initial_h;
    const float4* g_rh4c = (const float4*)g_rh;
    const int     slot   = kc & 3;
    const int     msel   = kc >> 2;       // valid when kc < 16

    __syncthreads();

    for (int t = 0; t < TT; t++) {
        const unsigned mask = rbits[t];
        const float4* base4 = (t == 0) ? (const float4*)carry : (const float4*)out;
        const int     off4  = (t == 0) ? 0 : (t - 1) * (HH / 4);

        // gx prefetch (combine threads), in flight behind staging
        float gxz = 0.f, gxr = 0.f, gxa = 0.f;
        if (tid < 128) {
            size_t gb = ((size_t)(n_c * TT + t)) * G3 + jbase + j_c;
            gxz = __ldcg(g_gx + gb);
            gxr = __ldcg(g_gx + gb + HH);
            gxa = __ldcg(g_gx + gb + 2 * HH);
        }

        // ---- stage h_in ----
#pragma unroll
        for (int r0 = 0; r0 < 8; r0 += 4) {
            float4 v[4];
#pragma unroll
            for (int p = 0; p < 4; p++) {
                int q  = tid + ((r0 + p) << 9);
                int n  = q >> 8;
                int kf = q & 255;
                if ((mask >> n) & 1u)
                    v[p] = ih4[kf];
                else
                    v[p] = __ldcg(base4 + (size_t)n * (TT * HH / 4) + off4 + kf);
            }
#pragma unroll
            for (int p = 0; p < 4; p++)
                hs4[tid + ((r0 + p) << 9)] = v[p];
        }
        __syncthreads();

        // ---- phase A: z,r dots, packed k ----
#pragma unroll
        for (int pass = 0; pass < 4; pass++) {
            u64 az[4], ar[4];
#pragma unroll
            for (int m = 0; m < 4; m++) { az[m] = 0ull; ar[m] = 0ull; }
#pragma unroll
            for (int m = 0; m < 4; m++) {
                const int n = (pass << 2) + m;
#pragma unroll
                for (int i = 0; i < 4; i++) {
                    ulonglong2 hv = *(const ulonglong2*)
                        &hs4[(n << 8) + (khalf << 7) + (i << 5) + kc];
                    fma2(az[m], hv.x, wz2[i * 2]);
                    fma2(ar[m], hv.x, wr2[i * 2]);
                    fma2(az[m], hv.y, wz2[i * 2 + 1]);
                    fma2(ar[m], hv.y, wr2[i * 2 + 1]);
                }
            }
            float zf[4], rf4[4];
#pragma unroll
            for (int m = 0; m < 4; m++) {
                float2 a = unpk(az[m]); zf[m]  = a.x + a.y;
                float2 b = unpk(ar[m]); rf4[m] = b.x + b.y;
            }
#pragma unroll
            for (int m = 0; m < 4; m++) {
#pragma unroll
                for (int off = 16; off > 2; off >>= 1) {
                    zf[m]  += __shfl_xor_sync(0xffffffffu, zf[m],  off);
                    rf4[m] += __shfl_xor_sync(0xffffffffu, rf4[m], off);
                }
            }
            if (kc < 16) {
                float zs = 0.f, rs = 0.f;
#pragma unroll
                for (int m = 0; m < 4; m++)
                    if (msel == m) { zs = zf[m]; rs = rf4[m]; }
                int n = (pass << 2) + msel;
                pzr[(((khalf << 3) + jw) * 16 + n) * 4 + slot] = make_float2(zs, rs);
            }
        }
        __syncthreads();

        // ---- combine A ----
        if (tid < 128) {
            float zsum = 0.f, rsum = 0.f;
            int b0 = (j_c * 16 + n_c) * 4;
            int b1 = ((8 + j_c) * 16 + n_c) * 4;
#pragma unroll
            for (int s = 0; s < 4; s++) {
                float2 q0 = pzr[b0 + s];
                float2 q1 = pzr[b1 + s];
                zsum += q0.x + q1.x;
                rsum += q0.y + q1.y;
            }
            float hold = hs[(n_c << 10) + jbase + j_c];
            float z = 1.f / (1.f + __expf(-(gxz + zsum + bz)));
            float r = 1.f / (1.f + __expf(-(gxr + rsum + br)));
            g_rh[(n_c << 10) + jbase + j_c] = r * hold;
            z_keep = z;
            h_keep = hold;
        }

        grid_barrier((unsigned)(2 * t + 1) * NCTA);

        // ---- stage r*h ----
#pragma unroll
        for (int r0 = 0; r0 < 8; r0 += 4) {
            float4 v[4];
#pragma unroll
            for (int p = 0; p < 4; p++)
                v[p] = __ldcg(g_rh4c + tid + ((r0 + p) << 9));
#pragma unroll
            for (int p = 0; p < 4; p++)
                rhs4[tid + ((r0 + p) << 9)] = v[p];
        }
        __syncthreads();

        // ---- phase B: a-gate dots ----
#pragma unroll
        for (int pass = 0; pass < 4; pass++) {
            u64 aa[4];
#pragma unroll
            for (int m = 0; m < 4; m++) aa[m] = 0ull;
#pragma unroll
            for (int m = 0; m < 4; m++) {
                const int n = (pass << 2) + m;
#pragma unroll
                for (int i = 0; i < 4; i++) {
                    ulonglong2 hv = *(const ulonglong2*)
                        &rhs4[(n << 8) + (khalf << 7) + (i << 5) + kc];
                    fma2(aa[m], hv.x, wa2[i * 2]);
                    fma2(aa[m], hv.y, wa2[i * 2 + 1]);
                }
            }
            float af[4];
#pragma unroll
            for (int m = 0; m < 4; m++) {
                float2 a = unpk(aa[m]); af[m] = a.x + a.y;
            }
#pragma unroll
            for (int m = 0; m < 4; m++) {
#pragma unroll
                for (int off = 16; off > 2; off >>= 1)
                    af[m] += __shfl_xor_sync(0xffffffffu, af[m], off);
            }
            if (kc < 16) {
                float as = 0.f;
#pragma unroll
                for (int m = 0; m < 4; m++)
                    if (msel == m) as = af[m];
                int n = (pass << 2) + msel;
                pa[(((khalf << 3) + jw) * 16 + n) * 4 + slot] = as;
            }
        }
        __syncthreads();

        // ---- combine B ----
        if (tid < 128) {
            float asum = 0.f;
            int b0 = (j_c * 16 + n_c) * 4;
            int b1 = ((8 + j_c) * 16 + n_c) * 4;
#pragma unroll
            for (int s = 0; s < 4; s++)
                asum += pa[b0 + s] + pa[b1 + s];
            float a  = tanhf(gxa + asum + ba);
            float hn = (1.f - z_keep) * h_keep + z_keep * a;
            size_t oidx = ((size_t)(n_c * TT + t)) * HH + jbase + j_c;
            out[oidx]             = hn;
            out[NTH_ELEMS + oidx] = hn;
        }

        grid_barrier((unsigned)(2 * t + 2) * NCTA);
    }
}

// ---------------------------------------------------------------------------
extern "C" void kernel_launch(void* const* d_in, const int* in_sizes, int n_in,
                              void* d_out, int out_size) {
    const float* x         = (const float*)d_in[0];
    const void*  reset     = d_in[1];
    const float* carry     = (const float*)d_in[2];
    const float* initial_h = (const float*)d_in[3];
    const float* w_i       = (const float*)d_in[4];
    const float* w_h       = (const float*)d_in[5];
    const float* b         = (const float*)d_in[6];
    float*       out       = (float*)d_out;
    (void)in_sizes; (void)n_in; (void)out_size;

    dim3 ggrid(G3 / 128, (NB * TT) / 128);
    gx_gemm_kernel<<<ggrid, 256>>>(x, w_i);

    size_t smem = 147456;
    cudaFuncSetAttribute((const void*)gru_scan_kernel,
                         cudaFuncAttributeMaxDynamicSharedMemorySize, (int)smem);
    gru_scan_kernel<<<NCTA, STHR, smem>>>(reset, carry, initial_h, w_h, b, out);
}